// round 4
// baseline (speedup 1.0000x reference)
#include <cuda_runtime.h>
#include <cuda_bf16.h>
#include <cstdint>

#define T_TOK 8192
#define HID   1536
#define NEXP  32
#define TOPK  8
#define INTER 512
#define N1    (2*INTER)       // 1024
#define MAXP  (T_TOK*TOPK)    // 65536

#define KSLAB 32
#define STAGE_BYTES 32768     // Ah8K + Al8K + Bh8K + Bl8K
#define NSTAGE 3
#define SMEM_TOTAL (2048 + NSTAGE*STAGE_BYTES)

// ---------------- device scratch ----------------
__device__ int   g_counts[NEXP];
__device__ int   g_list[NEXP * T_TOK];
__device__ float g_pairw[MAXP];
__device__ __nv_bfloat16 g_xh[(size_t)T_TOK * HID];
__device__ __nv_bfloat16 g_xl[(size_t)T_TOK * HID];
__device__ __nv_bfloat16 g_w13h[(size_t)NEXP * N1 * HID];
__device__ __nv_bfloat16 g_w13l[(size_t)NEXP * N1 * HID];
__device__ __nv_bfloat16 g_w2h[(size_t)NEXP * HID * INTER];
__device__ __nv_bfloat16 g_w2l[(size_t)NEXP * HID * INTER];
__device__ __nv_bfloat16 g_hh[(size_t)MAXP * INTER];
__device__ __nv_bfloat16 g_hl[(size_t)MAXP * INTER];
__device__ float g_y[(size_t)MAXP * HID];

// ---------------- PTX helpers (sm_103-baseline safe) ----------------
__device__ __forceinline__ uint32_t smem_u32(const void* p) {
    uint32_t a;
    asm("{ .reg .u64 t; cvta.to.shared.u64 t, %1; cvt.u32.u64 %0, t; }" : "=r"(a) : "l"(p));
    return a;
}
__device__ __forceinline__ uint32_t swz64(uint32_t b) { return b ^ ((b >> 3) & 0x30); }

__device__ __forceinline__ void cp16(uint32_t dst, const void* src, bool valid) {
    int sz = valid ? 16 : 0;
    asm volatile("cp.async.cg.shared.global [%0], [%1], 16, %2;\n" :: "r"(dst), "l"(src), "r"(sz));
}
__device__ __forceinline__ void cp_commit() { asm volatile("cp.async.commit_group;" ::: "memory"); }
template <int N> __device__ __forceinline__ void cp_wait() {
    asm volatile("cp.async.wait_group %0;" :: "n"(N) : "memory");
}
__device__ __forceinline__ void ldsm4(uint32_t* r, uint32_t addr) {
    asm volatile("ldmatrix.sync.aligned.m8n8.x4.shared.b16 {%0,%1,%2,%3}, [%4];"
                 : "=r"(r[0]), "=r"(r[1]), "=r"(r[2]), "=r"(r[3]) : "r"(addr));
}
__device__ __forceinline__ void mma16816(float* c, const uint32_t* a, const uint32_t* b) {
    asm volatile("mma.sync.aligned.m16n8k16.row.col.f32.bf16.bf16.f32 "
                 "{%0,%1,%2,%3}, {%4,%5,%6,%7}, {%8,%9}, {%0,%1,%2,%3};"
                 : "+f"(c[0]), "+f"(c[1]), "+f"(c[2]), "+f"(c[3])
                 : "r"(a[0]), "r"(a[1]), "r"(a[2]), "r"(a[3]), "r"(b[0]), "r"(b[1]));
}
__device__ __forceinline__ unsigned short bfbits(float f) {
    __nv_bfloat16 b = __float2bfloat16(f);
    return *reinterpret_cast<unsigned short*>(&b);
}

// ---------------- reset ----------------
__global__ void reset_kernel() {
    if (threadIdx.x < NEXP) g_counts[threadIdx.x] = 0;
}

// ---------------- fp32 -> bf16 hi/lo split ----------------
__device__ __forceinline__ void cvt_body(const float4* __restrict__ src, uint2* __restrict__ hi,
                                         uint2* __restrict__ lo, int n4) {
    int i = blockIdx.x * blockDim.x + threadIdx.x;
    if (i >= n4) return;
    float4 v = src[i];
    __nv_bfloat16 h0 = __float2bfloat16(v.x), h1 = __float2bfloat16(v.y);
    __nv_bfloat16 h2 = __float2bfloat16(v.z), h3 = __float2bfloat16(v.w);
    float r0 = v.x - __bfloat162float(h0), r1 = v.y - __bfloat162float(h1);
    float r2 = v.z - __bfloat162float(h2), r3 = v.w - __bfloat162float(h3);
    uint2 hv, lv;
    hv.x = (uint32_t)*reinterpret_cast<unsigned short*>(&h0) | ((uint32_t)*reinterpret_cast<unsigned short*>(&h1) << 16);
    hv.y = (uint32_t)*reinterpret_cast<unsigned short*>(&h2) | ((uint32_t)*reinterpret_cast<unsigned short*>(&h3) << 16);
    lv.x = (uint32_t)bfbits(r0) | ((uint32_t)bfbits(r1) << 16);
    lv.y = (uint32_t)bfbits(r2) | ((uint32_t)bfbits(r3) << 16);
    hi[i] = hv;
    lo[i] = lv;
}
__global__ void cvt_x_kernel(const float* __restrict__ x) {
    cvt_body((const float4*)x, (uint2*)g_xh, (uint2*)g_xl, T_TOK * HID / 4);
}
__global__ void cvt_w13_kernel(const float* __restrict__ w) {
    cvt_body((const float4*)w, (uint2*)g_w13h, (uint2*)g_w13l, NEXP * N1 * HID / 4);
}
__global__ void cvt_w2_kernel(const float* __restrict__ w) {
    cvt_body((const float4*)w, (uint2*)g_w2h, (uint2*)g_w2l, NEXP * HID * INTER / 4);
}

// ---------------- Router: one warp per token (fp32, exact) ----------------
__global__ __launch_bounds__(256) void router_kernel(const float* __restrict__ x,
                                                     const float* __restrict__ gw) {
    const unsigned FULL = 0xffffffffu;
    int warp = (blockIdx.x * blockDim.x + threadIdx.x) >> 5;
    int lane = threadIdx.x & 31;
    if (warp >= T_TOK) return;
    const int t = warp;
    const float4* x4 = (const float4*)(x + (size_t)t * HID);

    float logit = 0.f;
    for (int e = 0; e < NEXP; e++) {
        const float4* g4 = (const float4*)(gw + (size_t)e * HID);
        float s = 0.f;
        for (int k = lane; k < HID / 4; k += 32) {
            float4 a = x4[k], b = g4[k];
            s += a.x * b.x + a.y * b.y + a.z * b.z + a.w * b.w;
        }
        #pragma unroll
        for (int off = 16; off; off >>= 1) s += __shfl_xor_sync(FULL, s, off);
        if (lane == e) logit = s;
    }
    float m = logit;
    #pragma unroll
    for (int off = 16; off; off >>= 1) m = fmaxf(m, __shfl_xor_sync(FULL, m, off));
    float p = expf(logit - m);
    float sum = p;
    #pragma unroll
    for (int off = 16; off; off >>= 1) sum += __shfl_xor_sync(FULL, sum, off);
    p = p / sum;

    float keep = p, topsum = 0.f;
    int myslot = -1;
    for (int s = 0; s < TOPK; s++) {
        float v = keep; int bl = lane;
        #pragma unroll
        for (int off = 16; off; off >>= 1) {
            float ov = __shfl_down_sync(FULL, v, off);
            int   ol = __shfl_down_sync(FULL, bl, off);
            if (ov > v || (ov == v && ol < bl)) { v = ov; bl = ol; }
        }
        bl = __shfl_sync(FULL, bl, 0);
        v  = __shfl_sync(FULL, v, 0);
        topsum += v;
        if (lane == bl) { myslot = s; keep = -1.f; }
    }
    if (myslot >= 0) {
        int pos = atomicAdd(&g_counts[lane], 1);
        g_list[lane * T_TOK + pos] = t * TOPK + myslot;
        g_pairw[t * TOPK + myslot] = p / topsum;
    }
}

// ================= HMMA GEMM core: 512 threads, warp grid 4x4, warp tile 32x32 =================
// CTA tile 128(M) x 128(N), K-slab 32, 3-stage cp.async pipeline, SW64 swizzle (64B rows).
// Split bf16 3-pass: Ah*Bh + Ah*Bl + Al*Bh, fp32 accum.

__device__ __forceinline__ void slab_mma(uint32_t st, int warp_m, int warp_n, int lane,
                                         float acc[2][4][4]) {
    const uint32_t sAh = st, sAl = st + 8192, sBh = st + 16384, sBl = st + 24576;
    const uint32_t a_row = warp_m * 32 + (lane & 15);
    const uint32_t a_kb  = (lane >> 4) * 16;
    const uint32_t b_row = warp_n * 32 + (lane & 7) + ((lane >> 4) << 3);
    const uint32_t b_kb  = ((lane >> 3) & 1) * 16;
    #pragma unroll
    for (int ks = 0; ks < 2; ks++) {
        uint32_t ah[2][4], al[2][4], bh[4][2], bl[4][2];
        #pragma unroll
        for (int m = 0; m < 2; m++) {
            uint32_t off = (a_row + m * 16) * 64 + ks * 32 + a_kb;
            ldsm4(ah[m], sAh + swz64(off));
            ldsm4(al[m], sAl + swz64(off));
        }
        #pragma unroll
        for (int j = 0; j < 2; j++) {
            uint32_t off = (b_row + j * 16) * 64 + ks * 32 + b_kb;
            uint32_t t[4];
            ldsm4(t, sBh + swz64(off));
            bh[2*j][0] = t[0]; bh[2*j][1] = t[1]; bh[2*j+1][0] = t[2]; bh[2*j+1][1] = t[3];
            ldsm4(t, sBl + swz64(off));
            bl[2*j][0] = t[0]; bl[2*j][1] = t[1]; bl[2*j+1][0] = t[2]; bl[2*j+1][1] = t[3];
        }
        #pragma unroll
        for (int m = 0; m < 2; m++)
            #pragma unroll
            for (int n = 0; n < 4; n++) {
                mma16816(acc[m][n], ah[m], bh[n]);
                mma16816(acc[m][n], ah[m], bl[n]);
                mma16816(acc[m][n], al[m], bh[n]);
            }
    }
}

// ---------------- GEMM1: gathered x @ w13^T, fused SiLU*up -> bf16 hi/lo h ----------------
// n-tile t in 0..7: B rows 0..63 = gate rows [t*64, t*64+64), rows 64..127 = up rows [512+t*64, ...)
__global__ __launch_bounds__(512) void gemm1_mma() {
    const int e  = blockIdx.z;
    const int M  = g_counts[e];
    const int m0 = blockIdx.y * 128;
    if (m0 >= M) return;
    const int t = blockIdx.x;

    extern __shared__ char dsm[];
    int* s_pair = (int*)dsm;
    const uint32_t base = smem_u32(dsm);
    const uint32_t TILE = (base + 2047u) & ~1023u;   // >= base+1024, 1024-aligned
    float* sC = (float*)(dsm + (TILE - base));       // epilogue exchange, aliases stages

    const int tid = threadIdx.x, wid = tid >> 5, lane = tid & 31;
    const int warp_m = wid >> 2, warp_n = wid & 3;

    if (tid < 128) {
        int gr = m0 + tid;
        s_pair[tid] = (gr < M) ? g_list[e * T_TOK + gr] : -1;
    }
    __syncthreads();

    // copy slots: 512 16B chunks per matrix, 1 per thread
    const int r = tid >> 2, cw = tid & 3;
    const int p_r = s_pair[r];
    const bool vA = (p_r >= 0);
    const size_t offA = (size_t)(vA ? (p_r >> 3) : 0) * HID + cw * 8;
    const int brow = (r < 64) ? (t * 64 + r) : (512 + t * 64 + (r - 64));
    const size_t offB = ((size_t)e * N1 + brow) * HID + cw * 8;
    const uint32_t dst = swz64(r * 64 + cw * 16);

    auto load_stage = [&](int b, int k0) {
        uint32_t st = TILE + b * STAGE_BYTES;
        cp16(st + dst,         g_xh   + offA + k0, vA);
        cp16(st + 8192 + dst,  g_xl   + offA + k0, vA);
        cp16(st + 16384 + dst, g_w13h + offB + k0, true);
        cp16(st + 24576 + dst, g_w13l + offB + k0, true);
        cp_commit();
    };

    float acc[2][4][4];
    #pragma unroll
    for (int m = 0; m < 2; m++)
        #pragma unroll
        for (int n = 0; n < 4; n++)
            #pragma unroll
            for (int k = 0; k < 4; k++) acc[m][n][k] = 0.f;

    const int S = HID / KSLAB;  // 48
    load_stage(0, 0);
    load_stage(1, KSLAB);
    load_stage(2, 2 * KSLAB);
    for (int s = 0; s < S; s++) {
        if (s + 2 < S) cp_wait<2>(); else if (s + 1 < S) cp_wait<1>(); else cp_wait<0>();
        __syncthreads();
        slab_mma(TILE + (s % NSTAGE) * STAGE_BYTES, warp_m, warp_n, lane, acc);
        __syncthreads();
        if (s + 3 < S) load_stage((s + 3) % NSTAGE, (s + 3) * KSLAB);
    }

    // epilogue: exchange via smem, then h = silu(gate)*up -> bf16 hi/lo
    const int g = lane >> 2, tg = lane & 3;
    #pragma unroll
    for (int m = 0; m < 2; m++) {
        int r0 = warp_m * 32 + m * 16 + g;
        #pragma unroll
        for (int n = 0; n < 4; n++) {
            int col = warp_n * 32 + n * 8 + tg * 2;
            sC[r0 * 132 + col]       = acc[m][n][0];
            sC[r0 * 132 + col + 1]   = acc[m][n][1];
            sC[(r0+8) * 132 + col]   = acc[m][n][2];
            sC[(r0+8) * 132 + col+1] = acc[m][n][3];
        }
    }
    __syncthreads();

    {
        const int rr = tid >> 2, cb = (tid & 3) * 16;
        const int p = s_pair[rr];
        if (p >= 0) {
            uint32_t hp[8], lp[8];
            #pragma unroll
            for (int j = 0; j < 8; j++) {
                float g0 = sC[rr * 132 + cb + 2*j],      g1 = sC[rr * 132 + cb + 2*j + 1];
                float u0 = sC[rr * 132 + 64 + cb + 2*j], u1 = sC[rr * 132 + 64 + cb + 2*j + 1];
                float h0 = g0 / (1.f + expf(-g0)) * u0;
                float h1 = g1 / (1.f + expf(-g1)) * u1;
                __nv_bfloat16 b0 = __float2bfloat16(h0), b1 = __float2bfloat16(h1);
                hp[j] = (uint32_t)*reinterpret_cast<unsigned short*>(&b0) |
                        ((uint32_t)*reinterpret_cast<unsigned short*>(&b1) << 16);
                lp[j] = (uint32_t)bfbits(h0 - __bfloat162float(b0)) |
                        ((uint32_t)bfbits(h1 - __bfloat162float(b1)) << 16);
            }
            size_t o = (size_t)p * INTER + t * 64 + cb;
            uint4* dh = (uint4*)(g_hh + o);
            uint4* dl = (uint4*)(g_hl + o);
            dh[0] = make_uint4(hp[0], hp[1], hp[2], hp[3]);
            dh[1] = make_uint4(hp[4], hp[5], hp[6], hp[7]);
            dl[0] = make_uint4(lp[0], lp[1], lp[2], lp[3]);
            dl[1] = make_uint4(lp[4], lp[5], lp[6], lp[7]);
        }
    }
}

// ---------------- GEMM2: gathered h @ w2^T -> g_y (scaled by routing weight) ----------------
__global__ __launch_bounds__(512) void gemm2_mma() {
    const int e  = blockIdx.z;
    const int M  = g_counts[e];
    const int m0 = blockIdx.y * 128;
    if (m0 >= M) return;
    const int n0 = blockIdx.x * 128;

    extern __shared__ char dsm[];
    int* s_pair = (int*)dsm;
    const uint32_t base = smem_u32(dsm);
    const uint32_t TILE = (base + 2047u) & ~1023u;

    const int tid = threadIdx.x, wid = tid >> 5, lane = tid & 31;
    const int warp_m = wid >> 2, warp_n = wid & 3;

    if (tid < 128) {
        int gr = m0 + tid;
        s_pair[tid] = (gr < M) ? g_list[e * T_TOK + gr] : -1;
    }
    __syncthreads();

    const int r = tid >> 2, cw = tid & 3;
    const int p_r = s_pair[r];
    const bool vA = (p_r >= 0);
    const size_t offA = (size_t)(vA ? p_r : 0) * INTER + cw * 8;
    const size_t offB = ((size_t)e * HID + n0 + r) * INTER + cw * 8;
    const uint32_t dst = swz64(r * 64 + cw * 16);

    auto load_stage = [&](int b, int k0) {
        uint32_t st = TILE + b * STAGE_BYTES;
        cp16(st + dst,         g_hh  + offA + k0, vA);
        cp16(st + 8192 + dst,  g_hl  + offA + k0, vA);
        cp16(st + 16384 + dst, g_w2h + offB + k0, true);
        cp16(st + 24576 + dst, g_w2l + offB + k0, true);
        cp_commit();
    };

    float acc[2][4][4];
    #pragma unroll
    for (int m = 0; m < 2; m++)
        #pragma unroll
        for (int n = 0; n < 4; n++)
            #pragma unroll
            for (int k = 0; k < 4; k++) acc[m][n][k] = 0.f;

    const int S = INTER / KSLAB;  // 16
    load_stage(0, 0);
    load_stage(1, KSLAB);
    load_stage(2, 2 * KSLAB);
    for (int s = 0; s < S; s++) {
        if (s + 2 < S) cp_wait<2>(); else if (s + 1 < S) cp_wait<1>(); else cp_wait<0>();
        __syncthreads();
        slab_mma(TILE + (s % NSTAGE) * STAGE_BYTES, warp_m, warp_n, lane, acc);
        __syncthreads();
        if (s + 3 < S) load_stage((s + 3) % NSTAGE, (s + 3) * KSLAB);
    }

    const int g = lane >> 2, tg = lane & 3;
    #pragma unroll
    for (int m = 0; m < 2; m++) {
        int lr = warp_m * 32 + m * 16 + g;
        int p0 = s_pair[lr], p1 = s_pair[lr + 8];
        float w0 = (p0 >= 0) ? g_pairw[p0] : 0.f;
        float w1 = (p1 >= 0) ? g_pairw[p1] : 0.f;
        #pragma unroll
        for (int n = 0; n < 4; n++) {
            int col = n0 + warp_n * 32 + n * 8 + tg * 2;
            if (p0 >= 0) *(float2*)(g_y + (size_t)p0 * HID + col) = make_float2(w0 * acc[m][n][0], w0 * acc[m][n][1]);
            if (p1 >= 0) *(float2*)(g_y + (size_t)p1 * HID + col) = make_float2(w1 * acc[m][n][2], w1 * acc[m][n][3]);
        }
    }
}

// ---------------- deterministic 8-slot reduction ----------------
__global__ void reduce_kernel(float* __restrict__ out) {
    size_t idx = (size_t)blockIdx.x * blockDim.x + threadIdx.x;
    const size_t total = (size_t)T_TOK * (HID / 4);
    if (idx >= total) return;
    size_t t = idx / (HID / 4);
    int    c = (int)(idx % (HID / 4));
    const float4* base = (const float4*)(g_y + t * (size_t)TOPK * HID) + c;
    float4 s = make_float4(0.f, 0.f, 0.f, 0.f);
    #pragma unroll
    for (int sl = 0; sl < TOPK; sl++) {
        float4 v = base[(size_t)sl * (HID / 4)];
        s.x += v.x; s.y += v.y; s.z += v.z; s.w += v.w;
    }
    ((float4*)out)[idx] = s;
}

extern "C" void kernel_launch(void* const* d_in, const int* in_sizes, int n_in,
                              void* d_out, int out_size) {
    (void)in_sizes; (void)n_in; (void)out_size;
    const float* x   = (const float*)d_in[0];
    const float* gw  = (const float*)d_in[1];
    const float* w13 = (const float*)d_in[2];
    const float* w2  = (const float*)d_in[3];
    float* out = (float*)d_out;

    cudaFuncSetAttribute(gemm1_mma, cudaFuncAttributeMaxDynamicSharedMemorySize, SMEM_TOTAL);
    cudaFuncSetAttribute(gemm2_mma, cudaFuncAttributeMaxDynamicSharedMemorySize, SMEM_TOTAL);

    reset_kernel<<<1, 32>>>();
    cvt_x_kernel<<<(T_TOK * HID / 4 + 255) / 256, 256>>>(x);
    cvt_w13_kernel<<<(NEXP * N1 * HID / 4 + 255) / 256, 256>>>(w13);
    cvt_w2_kernel<<<(NEXP * HID * INTER / 4 + 255) / 256, 256>>>(w2);
    router_kernel<<<T_TOK / 8, 256>>>(x, gw);
    gemm1_mma<<<dim3(8, 64, NEXP), 512, SMEM_TOTAL>>>();
    gemm2_mma<<<dim3(HID / 128, 64, NEXP), 512, SMEM_TOTAL>>>();
    reduce_kernel<<<(int)(((size_t)T_TOK * (HID / 4)) / 256), 256>>>(out);
}

// round 6
// speedup vs baseline: 1.1935x; 1.1935x over previous
#include <cuda_runtime.h>
#include <cuda_bf16.h>
#include <cstdint>

#define T_TOK 8192
#define HID   1536
#define NEXP  32
#define TOPK  8
#define INTER 512
#define N1    (2*INTER)       // 1024
#define MAXP  (T_TOK*TOPK)    // 65536

#define KSLAB 64
#define STAGE_BYTES 98304     // Ah16K + Al16K + Bh32K + Bl32K
#define SMEM_TOTAL  (1024 + 2*STAGE_BYTES)

// ---------------- device scratch ----------------
__device__ int   g_counts[NEXP];
__device__ int   g_list[NEXP * T_TOK];
__device__ float g_pairw[MAXP];
__device__ __nv_bfloat16 g_xh[(size_t)T_TOK * HID];
__device__ __nv_bfloat16 g_xl[(size_t)T_TOK * HID];
__device__ __nv_bfloat16 g_w13h[(size_t)NEXP * N1 * HID];
__device__ __nv_bfloat16 g_w13l[(size_t)NEXP * N1 * HID];
__device__ __nv_bfloat16 g_w2h[(size_t)NEXP * HID * INTER];
__device__ __nv_bfloat16 g_w2l[(size_t)NEXP * HID * INTER];
__device__ __nv_bfloat16 g_hh[(size_t)MAXP * INTER];
__device__ __nv_bfloat16 g_hl[(size_t)MAXP * INTER];
__device__ float g_y[(size_t)MAXP * HID];

// ---------------- PTX helpers (sm_103-baseline safe) ----------------
__device__ __forceinline__ uint32_t smem_u32(const void* p) {
    uint32_t a;
    asm("{ .reg .u64 t; cvta.to.shared.u64 t, %1; cvt.u32.u64 %0, t; }" : "=r"(a) : "l"(p));
    return a;
}
__device__ __forceinline__ uint32_t swz(uint32_t b) { return b ^ ((b >> 3) & 0x70); }

__device__ __forceinline__ void cp16(uint32_t dst, const void* src, bool valid) {
    int sz = valid ? 16 : 0;
    asm volatile("cp.async.cg.shared.global [%0], [%1], 16, %2;\n" :: "r"(dst), "l"(src), "r"(sz));
}
__device__ __forceinline__ void cp_commit() { asm volatile("cp.async.commit_group;" ::: "memory"); }
template <int N> __device__ __forceinline__ void cp_wait() {
    asm volatile("cp.async.wait_group %0;" :: "n"(N) : "memory");
}
__device__ __forceinline__ void ldsm4(uint32_t* r, uint32_t addr) {
    asm volatile("ldmatrix.sync.aligned.m8n8.x4.shared.b16 {%0,%1,%2,%3}, [%4];"
                 : "=r"(r[0]), "=r"(r[1]), "=r"(r[2]), "=r"(r[3]) : "r"(addr));
}
__device__ __forceinline__ void mma16816(float* c, const uint32_t* a, const uint32_t* b) {
    asm volatile("mma.sync.aligned.m16n8k16.row.col.f32.bf16.bf16.f32 "
                 "{%0,%1,%2,%3}, {%4,%5,%6,%7}, {%8,%9}, {%0,%1,%2,%3};"
                 : "+f"(c[0]), "+f"(c[1]), "+f"(c[2]), "+f"(c[3])
                 : "r"(a[0]), "r"(a[1]), "r"(a[2]), "r"(a[3]), "r"(b[0]), "r"(b[1]));
}
__device__ __forceinline__ unsigned short bfbits(float f) {
    __nv_bfloat16 b = __float2bfloat16(f);
    return *reinterpret_cast<unsigned short*>(&b);
}

// ---------------- reset ----------------
__global__ void reset_kernel() {
    if (threadIdx.x < NEXP) g_counts[threadIdx.x] = 0;
}

// ---------------- fp32 -> bf16 hi/lo split ----------------
__device__ __forceinline__ void cvt_body(const float4* __restrict__ src, uint2* __restrict__ hi,
                                         uint2* __restrict__ lo, int n4) {
    int i = blockIdx.x * blockDim.x + threadIdx.x;
    if (i >= n4) return;
    float4 v = src[i];
    __nv_bfloat16 h0 = __float2bfloat16(v.x), h1 = __float2bfloat16(v.y);
    __nv_bfloat16 h2 = __float2bfloat16(v.z), h3 = __float2bfloat16(v.w);
    float r0 = v.x - __bfloat162float(h0), r1 = v.y - __bfloat162float(h1);
    float r2 = v.z - __bfloat162float(h2), r3 = v.w - __bfloat162float(h3);
    uint2 hv, lv;
    hv.x = (uint32_t)*reinterpret_cast<unsigned short*>(&h0) | ((uint32_t)*reinterpret_cast<unsigned short*>(&h1) << 16);
    hv.y = (uint32_t)*reinterpret_cast<unsigned short*>(&h2) | ((uint32_t)*reinterpret_cast<unsigned short*>(&h3) << 16);
    lv.x = (uint32_t)bfbits(r0) | ((uint32_t)bfbits(r1) << 16);
    lv.y = (uint32_t)bfbits(r2) | ((uint32_t)bfbits(r3) << 16);
    hi[i] = hv;
    lo[i] = lv;
}
__global__ void cvt_x_kernel(const float* __restrict__ x) {
    cvt_body((const float4*)x, (uint2*)g_xh, (uint2*)g_xl, T_TOK * HID / 4);
}
__global__ void cvt_w13_kernel(const float* __restrict__ w) {
    cvt_body((const float4*)w, (uint2*)g_w13h, (uint2*)g_w13l, NEXP * N1 * HID / 4);
}
__global__ void cvt_w2_kernel(const float* __restrict__ w) {
    cvt_body((const float4*)w, (uint2*)g_w2h, (uint2*)g_w2l, NEXP * HID * INTER / 4);
}

// ---------------- Router: one warp per token (fp32, exact) ----------------
__global__ __launch_bounds__(256) void router_kernel(const float* __restrict__ x,
                                                     const float* __restrict__ gw) {
    const unsigned FULL = 0xffffffffu;
    int warp = (blockIdx.x * blockDim.x + threadIdx.x) >> 5;
    int lane = threadIdx.x & 31;
    if (warp >= T_TOK) return;
    const int t = warp;
    const float4* x4 = (const float4*)(x + (size_t)t * HID);

    float logit = 0.f;
    for (int e = 0; e < NEXP; e++) {
        const float4* g4 = (const float4*)(gw + (size_t)e * HID);
        float s = 0.f;
        for (int k = lane; k < HID / 4; k += 32) {
            float4 a = x4[k], b = g4[k];
            s += a.x * b.x + a.y * b.y + a.z * b.z + a.w * b.w;
        }
        #pragma unroll
        for (int off = 16; off; off >>= 1) s += __shfl_xor_sync(FULL, s, off);
        if (lane == e) logit = s;
    }
    float m = logit;
    #pragma unroll
    for (int off = 16; off; off >>= 1) m = fmaxf(m, __shfl_xor_sync(FULL, m, off));
    float p = expf(logit - m);
    float sum = p;
    #pragma unroll
    for (int off = 16; off; off >>= 1) sum += __shfl_xor_sync(FULL, sum, off);
    p = p / sum;

    float keep = p, topsum = 0.f;
    int myslot = -1;
    for (int s = 0; s < TOPK; s++) {
        float v = keep; int bl = lane;
        #pragma unroll
        for (int off = 16; off; off >>= 1) {
            float ov = __shfl_down_sync(FULL, v, off);
            int   ol = __shfl_down_sync(FULL, bl, off);
            if (ov > v || (ov == v && ol < bl)) { v = ov; bl = ol; }
        }
        bl = __shfl_sync(FULL, bl, 0);
        v  = __shfl_sync(FULL, v, 0);
        topsum += v;
        if (lane == bl) { myslot = s; keep = -1.f; }
    }
    if (myslot >= 0) {
        int pos = atomicAdd(&g_counts[lane], 1);
        g_list[lane * T_TOK + pos] = t * TOPK + myslot;
        g_pairw[t * TOPK + myslot] = p / topsum;
    }
}

// ================= HMMA core: 256 threads, warp grid 2x4, warp tile 64x64 =================
// CTA tile 128(M) x 256(N), K-slab 64, 2-stage pipeline, SW128 swizzle (128B rows).
// Split bf16 3-pass: Ah*Bh + Ah*Bl + Al*Bh, fp32 accum. acc[4][8][4] per thread.

__device__ __forceinline__ void slab_mma(uint32_t st, int warp_m, int warp_n, int lane,
                                         float acc[4][8][4]) {
    const uint32_t sAh = st, sAl = st + 16384, sBh = st + 32768, sBl = st + 65536;
    const uint32_t a_row = warp_m * 64 + (lane & 15);
    const uint32_t a_kb  = (lane >> 4) * 16;
    const uint32_t b_row = warp_n * 64 + (lane & 7) + ((lane >> 4) << 3);
    const uint32_t b_kb  = ((lane >> 3) & 1) * 16;
    #pragma unroll
    for (int ks = 0; ks < 4; ks++) {
        uint32_t ah[4][4], al[4][4];
        #pragma unroll
        for (int m = 0; m < 4; m++) {
            uint32_t off = (a_row + m * 16) * 128 + ks * 32 + a_kb;
            ldsm4(ah[m], sAh + swz(off));
            ldsm4(al[m], sAl + swz(off));
        }
        #pragma unroll
        for (int j = 0; j < 4; j++) {
            uint32_t off = (b_row + j * 16) * 128 + ks * 32 + b_kb;
            uint32_t th[4], tl[4];
            ldsm4(th, sBh + swz(off));
            ldsm4(tl, sBl + swz(off));
            #pragma unroll
            for (int m = 0; m < 4; m++) {
                mma16816(acc[m][2*j],   ah[m], th);
                mma16816(acc[m][2*j],   ah[m], tl);
                mma16816(acc[m][2*j],   al[m], th);
                mma16816(acc[m][2*j+1], ah[m], th + 2);
                mma16816(acc[m][2*j+1], ah[m], tl + 2);
                mma16816(acc[m][2*j+1], al[m], th + 2);
            }
        }
    }
}

// ---------------- GEMM1: gathered x @ w13^T, fused SiLU*up -> bf16 hi/lo h ----------------
// n-tile t in 0..3: B rows 0..127 = gate rows [t*128,+128), rows 128..255 = up rows [512+t*128,+128)
__global__ __launch_bounds__(256, 1) void gemm1_mma() {
    const int e  = blockIdx.z;
    const int M  = g_counts[e];
    const int m0 = blockIdx.y * 128;
    if (m0 >= M) return;
    const int t = blockIdx.x;

    extern __shared__ char dsm[];
    int* s_pair = (int*)dsm;
    const uint32_t TILE = smem_u32(dsm) + 1024;
    float* sC = (float*)(dsm + 1024);   // 128x132 fp32 exchange (aliases stages after mainloop)

    const int tid = threadIdx.x, wid = tid >> 5, lane = tid & 31;
    const int warp_m = wid >> 2, warp_n = wid & 3;

    if (tid < 128) {
        int gr = m0 + tid;
        s_pair[tid] = (gr < M) ? g_list[e * T_TOK + gr] : -1;
    }
    __syncthreads();

    // copy slots: A 1024 chunks (4/thread), B 2048 chunks (8/thread); 32-bit offsets
    uint32_t offA[4]; uint32_t dstA[4]; bool vA[4];
    uint32_t offB[8]; uint32_t dstB[8];
    #pragma unroll
    for (int i = 0; i < 4; i++) {
        int c = tid + i * 256, r = c >> 3, cw = c & 7;
        int p = s_pair[r];
        vA[i] = (p >= 0);
        offA[i] = (uint32_t)(vA[i] ? (p >> 3) : 0) * HID + cw * 8;
        dstA[i] = swz(r * 128 + cw * 16);
    }
    #pragma unroll
    for (int i = 0; i < 8; i++) {
        int c = tid + i * 256, r = c >> 3, cw = c & 7;
        int brow = (r < 128) ? (t * 128 + r) : (512 + t * 128 + (r - 128));
        offB[i] = (uint32_t)((uint32_t)e * N1 + brow) * HID + cw * 8;
        dstB[i] = swz(r * 128 + cw * 16);
    }

    auto load_stage = [&](int b, int k0) {
        uint32_t st = TILE + b * STAGE_BYTES;
        #pragma unroll
        for (int i = 0; i < 4; i++) {
            cp16(st + dstA[i],         g_xh + offA[i] + k0, vA[i]);
            cp16(st + 16384 + dstA[i], g_xl + offA[i] + k0, vA[i]);
        }
        #pragma unroll
        for (int i = 0; i < 8; i++) {
            cp16(st + 32768 + dstB[i], g_w13h + offB[i] + k0, true);
            cp16(st + 65536 + dstB[i], g_w13l + offB[i] + k0, true);
        }
        cp_commit();
    };

    float acc[4][8][4];
    #pragma unroll
    for (int m = 0; m < 4; m++)
        #pragma unroll
        for (int n = 0; n < 8; n++)
            #pragma unroll
            for (int k = 0; k < 4; k++) acc[m][n][k] = 0.f;

    const int S = HID / KSLAB;  // 24
    load_stage(0, 0);
    load_stage(1, KSLAB);
    for (int s = 0; s < S; s++) {
        const int b = s & 1;
        if (s + 1 < S) cp_wait<1>(); else cp_wait<0>();
        __syncthreads();
        slab_mma(TILE + b * STAGE_BYTES, warp_m, warp_n, lane, acc);
        __syncthreads();
        if (s + 2 < S) load_stage(b, (s + 2) * KSLAB);
    }

    // ---- fused epilogue: gate warps (warp_n<2) stage C through smem; up warps emit h ----
    const int g = lane >> 2, tg = lane & 3;
    if (warp_n < 2) {
        #pragma unroll
        for (int m = 0; m < 4; m++) {
            int row = warp_m * 64 + m * 16 + g;
            #pragma unroll
            for (int n = 0; n < 8; n++) {
                int col = warp_n * 64 + n * 8 + tg * 2;
                sC[row * 132 + col]           = acc[m][n][0];
                sC[row * 132 + col + 1]       = acc[m][n][1];
                sC[(row + 8) * 132 + col]     = acc[m][n][2];
                sC[(row + 8) * 132 + col + 1] = acc[m][n][3];
            }
        }
    }
    __syncthreads();
    if (warp_n >= 2) {
        #pragma unroll
        for (int m = 0; m < 4; m++) {
            int row = warp_m * 64 + m * 16 + g;
            int p0 = s_pair[row], p1 = s_pair[row + 8];
            #pragma unroll
            for (int n = 0; n < 8; n++) {
                int ucol = (warp_n - 2) * 64 + n * 8 + tg * 2;
                if (p0 >= 0) {
                    float g0 = sC[row * 132 + ucol], g1 = sC[row * 132 + ucol + 1];
                    float h0 = g0 / (1.f + expf(-g0)) * acc[m][n][0];
                    float h1 = g1 / (1.f + expf(-g1)) * acc[m][n][1];
                    __nv_bfloat16 b0 = __float2bfloat16(h0), b1 = __float2bfloat16(h1);
                    uint32_t o = ((uint32_t)p0 * INTER + t * 128 + ucol) >> 1;
                    ((uint32_t*)g_hh)[o] = (uint32_t)*reinterpret_cast<unsigned short*>(&b0) |
                                           ((uint32_t)*reinterpret_cast<unsigned short*>(&b1) << 16);
                    ((uint32_t*)g_hl)[o] = (uint32_t)bfbits(h0 - __bfloat162float(b0)) |
                                           ((uint32_t)bfbits(h1 - __bfloat162float(b1)) << 16);
                }
                if (p1 >= 0) {
                    float g0 = sC[(row + 8) * 132 + ucol], g1 = sC[(row + 8) * 132 + ucol + 1];
                    float h0 = g0 / (1.f + expf(-g0)) * acc[m][n][2];
                    float h1 = g1 / (1.f + expf(-g1)) * acc[m][n][3];
                    __nv_bfloat16 b0 = __float2bfloat16(h0), b1 = __float2bfloat16(h1);
                    uint32_t o = ((uint32_t)p1 * INTER + t * 128 + ucol) >> 1;
                    ((uint32_t*)g_hh)[o] = (uint32_t)*reinterpret_cast<unsigned short*>(&b0) |
                                           ((uint32_t)*reinterpret_cast<unsigned short*>(&b1) << 16);
                    ((uint32_t*)g_hl)[o] = (uint32_t)bfbits(h0 - __bfloat162float(b0)) |
                                           ((uint32_t)bfbits(h1 - __bfloat162float(b1)) << 16);
                }
            }
        }
    }
}

// ---------------- GEMM2: gathered h @ w2^T -> g_y (scaled by routing weight) ----------------
__global__ __launch_bounds__(256, 1) void gemm2_mma() {
    const int e  = blockIdx.z;
    const int M  = g_counts[e];
    const int m0 = blockIdx.y * 128;
    if (m0 >= M) return;
    const int n0 = blockIdx.x * 256;

    extern __shared__ char dsm[];
    int* s_pair = (int*)dsm;
    const uint32_t TILE = smem_u32(dsm) + 1024;

    const int tid = threadIdx.x, wid = tid >> 5, lane = tid & 31;
    const int warp_m = wid >> 2, warp_n = wid & 3;

    if (tid < 128) {
        int gr = m0 + tid;
        s_pair[tid] = (gr < M) ? g_list[e * T_TOK + gr] : -1;
    }
    __syncthreads();

    uint32_t offA[4]; uint32_t dstA[4]; bool vA[4];
    uint32_t offB[8]; uint32_t dstB[8];
    #pragma unroll
    for (int i = 0; i < 4; i++) {
        int c = tid + i * 256, r = c >> 3, cw = c & 7;
        int p = s_pair[r];
        vA[i] = (p >= 0);
        offA[i] = (uint32_t)(vA[i] ? p : 0) * INTER + cw * 8;
        dstA[i] = swz(r * 128 + cw * 16);
    }
    #pragma unroll
    for (int i = 0; i < 8; i++) {
        int c = tid + i * 256, r = c >> 3, cw = c & 7;
        offB[i] = ((uint32_t)e * HID + n0 + r) * INTER + cw * 8;
        dstB[i] = swz(r * 128 + cw * 16);
    }

    auto load_stage = [&](int b, int k0) {
        uint32_t st = TILE + b * STAGE_BYTES;
        #pragma unroll
        for (int i = 0; i < 4; i++) {
            cp16(st + dstA[i],         g_hh + offA[i] + k0, vA[i]);
            cp16(st + 16384 + dstA[i], g_hl + offA[i] + k0, vA[i]);
        }
        #pragma unroll
        for (int i = 0; i < 8; i++) {
            cp16(st + 32768 + dstB[i], g_w2h + offB[i] + k0, true);
            cp16(st + 65536 + dstB[i], g_w2l + offB[i] + k0, true);
        }
        cp_commit();
    };

    float acc[4][8][4];
    #pragma unroll
    for (int m = 0; m < 4; m++)
        #pragma unroll
        for (int n = 0; n < 8; n++)
            #pragma unroll
            for (int k = 0; k < 4; k++) acc[m][n][k] = 0.f;

    const int S = INTER / KSLAB;  // 8
    load_stage(0, 0);
    load_stage(1, KSLAB);
    for (int s = 0; s < S; s++) {
        const int b = s & 1;
        if (s + 1 < S) cp_wait<1>(); else cp_wait<0>();
        __syncthreads();
        slab_mma(TILE + b * STAGE_BYTES, warp_m, warp_n, lane, acc);
        __syncthreads();
        if (s + 2 < S) load_stage(b, (s + 2) * KSLAB);
    }

    const int g = lane >> 2, tg = lane & 3;
    #pragma unroll
    for (int m = 0; m < 4; m++) {
        int lr = warp_m * 64 + m * 16 + g;
        int p0 = s_pair[lr], p1 = s_pair[lr + 8];
        float w0 = (p0 >= 0) ? g_pairw[p0] : 0.f;
        float w1 = (p1 >= 0) ? g_pairw[p1] : 0.f;
        #pragma unroll
        for (int n = 0; n < 8; n++) {
            int col = n0 + warp_n * 64 + n * 8 + tg * 2;
            if (p0 >= 0) *(float2*)(g_y + (size_t)p0 * HID + col) = make_float2(w0 * acc[m][n][0], w0 * acc[m][n][1]);
            if (p1 >= 0) *(float2*)(g_y + (size_t)p1 * HID + col) = make_float2(w1 * acc[m][n][2], w1 * acc[m][n][3]);
        }
    }
}

// ---------------- deterministic 8-slot reduction ----------------
__global__ void reduce_kernel(float* __restrict__ out) {
    size_t idx = (size_t)blockIdx.x * blockDim.x + threadIdx.x;
    const size_t total = (size_t)T_TOK * (HID / 4);
    if (idx >= total) return;
    size_t t = idx / (HID / 4);
    int    c = (int)(idx % (HID / 4));
    const float4* base = (const float4*)(g_y + t * (size_t)TOPK * HID) + c;
    float4 s = make_float4(0.f, 0.f, 0.f, 0.f);
    #pragma unroll
    for (int sl = 0; sl < TOPK; sl++) {
        float4 v = base[(size_t)sl * (HID / 4)];
        s.x += v.x; s.y += v.y; s.z += v.z; s.w += v.w;
    }
    ((float4*)out)[idx] = s;
}

extern "C" void kernel_launch(void* const* d_in, const int* in_sizes, int n_in,
                              void* d_out, int out_size) {
    (void)in_sizes; (void)n_in; (void)out_size;
    const float* x   = (const float*)d_in[0];
    const float* gw  = (const float*)d_in[1];
    const float* w13 = (const float*)d_in[2];
    const float* w2  = (const float*)d_in[3];
    float* out = (float*)d_out;

    cudaFuncSetAttribute(gemm1_mma, cudaFuncAttributeMaxDynamicSharedMemorySize, SMEM_TOTAL);
    cudaFuncSetAttribute(gemm2_mma, cudaFuncAttributeMaxDynamicSharedMemorySize, SMEM_TOTAL);

    reset_kernel<<<1, 32>>>();
    cvt_x_kernel<<<(T_TOK * HID / 4 + 255) / 256, 256>>>(x);
    cvt_w13_kernel<<<(NEXP * N1 * HID / 4 + 255) / 256, 256>>>(w13);
    cvt_w2_kernel<<<(NEXP * HID * INTER / 4 + 255) / 256, 256>>>(w2);
    router_kernel<<<T_TOK / 8, 256>>>(x, gw);
    gemm1_mma<<<dim3(INTER / 128, 64, NEXP), 256, SMEM_TOTAL>>>();
    gemm2_mma<<<dim3(HID / 256, 64, NEXP), 256, SMEM_TOTAL>>>();
    reduce_kernel<<<(int)(((size_t)T_TOK * (HID / 4)) / 256), 256>>>(out);
}

// round 7
// speedup vs baseline: 1.2960x; 1.0858x over previous
#include <cuda_runtime.h>
#include <cuda_fp16.h>
#include <cstdint>

#define T_TOK 8192
#define HID   1536
#define NEXP  32
#define TOPK  8
#define INTER 512
#define N1    (2*INTER)       // 1024
#define MAXP  (T_TOK*TOPK)    // 65536

#define KSLAB 32
#define ST1   40960           // GEMM1 stage: Ah8K + Bh16K + Bl16K
#define SMEM1 (1024 + 4*ST1)  // 164864
#define ST2   49152           // GEMM2 stage: Ah8K + Al8K + Bh16K + Bl16K
#define SMEM2 (1024 + 4*ST2)  // 197632

// ---------------- device scratch ----------------
__device__ int   g_counts[NEXP];
__device__ int   g_list[NEXP * T_TOK];
__device__ float g_pairw[MAXP];
__device__ __half g_xh[(size_t)T_TOK * HID];
__device__ __half g_w13h[(size_t)NEXP * N1 * HID];
__device__ __half g_w13l[(size_t)NEXP * N1 * HID];
__device__ __half g_w2h[(size_t)NEXP * HID * INTER];
__device__ __half g_w2l[(size_t)NEXP * HID * INTER];
__device__ __half g_hh[(size_t)MAXP * INTER];
__device__ __half g_hl[(size_t)MAXP * INTER];
__device__ float g_y[(size_t)MAXP * HID];

// ---------------- PTX helpers (sm_103-baseline safe) ----------------
__device__ __forceinline__ uint32_t smem_u32(const void* p) {
    uint32_t a;
    asm("{ .reg .u64 t; cvta.to.shared.u64 t, %1; cvt.u32.u64 %0, t; }" : "=r"(a) : "l"(p));
    return a;
}
__device__ __forceinline__ uint32_t swz64(uint32_t b) { return b ^ ((b >> 3) & 0x30); }

__device__ __forceinline__ void cp16(uint32_t dst, const void* src, bool valid) {
    int sz = valid ? 16 : 0;
    asm volatile("cp.async.cg.shared.global [%0], [%1], 16, %2;\n" :: "r"(dst), "l"(src), "r"(sz));
}
__device__ __forceinline__ void cp_commit() { asm volatile("cp.async.commit_group;" ::: "memory"); }
template <int N> __device__ __forceinline__ void cp_wait() {
    asm volatile("cp.async.wait_group %0;" :: "n"(N) : "memory");
}
__device__ __forceinline__ void ldsm4(uint32_t* r, uint32_t addr) {
    asm volatile("ldmatrix.sync.aligned.m8n8.x4.shared.b16 {%0,%1,%2,%3}, [%4];"
                 : "=r"(r[0]), "=r"(r[1]), "=r"(r[2]), "=r"(r[3]) : "r"(addr));
}
__device__ __forceinline__ void mma_f16(float* c, const uint32_t* a, const uint32_t* b) {
    asm volatile("mma.sync.aligned.m16n8k16.row.col.f32.f16.f16.f32 "
                 "{%0,%1,%2,%3}, {%4,%5,%6,%7}, {%8,%9}, {%0,%1,%2,%3};"
                 : "+f"(c[0]), "+f"(c[1]), "+f"(c[2]), "+f"(c[3])
                 : "r"(a[0]), "r"(a[1]), "r"(a[2]), "r"(a[3]), "r"(b[0]), "r"(b[1]));
}
__device__ __forceinline__ unsigned short hfbits(float f) {
    __half h = __float2half_rn(f);
    return *reinterpret_cast<unsigned short*>(&h);
}

// ---------------- reset ----------------
__global__ void reset_kernel() {
    if (threadIdx.x < NEXP) g_counts[threadIdx.x] = 0;
}

// ---------------- fp32 -> fp16 hi/lo split ----------------
__device__ __forceinline__ void cvt_pair(const float4* __restrict__ src, uint2* __restrict__ hi,
                                         uint2* __restrict__ lo, int n4) {
    int i = blockIdx.x * blockDim.x + threadIdx.x;
    if (i >= n4) return;
    float4 v = src[i];
    __half h0 = __float2half_rn(v.x), h1 = __float2half_rn(v.y);
    __half h2 = __float2half_rn(v.z), h3 = __float2half_rn(v.w);
    float r0 = v.x - __half2float(h0), r1 = v.y - __half2float(h1);
    float r2 = v.z - __half2float(h2), r3 = v.w - __half2float(h3);
    uint2 hv, lv;
    hv.x = (uint32_t)*reinterpret_cast<unsigned short*>(&h0) | ((uint32_t)*reinterpret_cast<unsigned short*>(&h1) << 16);
    hv.y = (uint32_t)*reinterpret_cast<unsigned short*>(&h2) | ((uint32_t)*reinterpret_cast<unsigned short*>(&h3) << 16);
    lv.x = (uint32_t)hfbits(r0) | ((uint32_t)hfbits(r1) << 16);
    lv.y = (uint32_t)hfbits(r2) | ((uint32_t)hfbits(r3) << 16);
    hi[i] = hv;
    lo[i] = lv;
}
__global__ void cvt_x_kernel(const float* __restrict__ x) {
    int i = blockIdx.x * blockDim.x + threadIdx.x;
    if (i >= T_TOK * HID / 4) return;
    float4 v = ((const float4*)x)[i];
    __half h0 = __float2half_rn(v.x), h1 = __float2half_rn(v.y);
    __half h2 = __float2half_rn(v.z), h3 = __float2half_rn(v.w);
    uint2 hv;
    hv.x = (uint32_t)*reinterpret_cast<unsigned short*>(&h0) | ((uint32_t)*reinterpret_cast<unsigned short*>(&h1) << 16);
    hv.y = (uint32_t)*reinterpret_cast<unsigned short*>(&h2) | ((uint32_t)*reinterpret_cast<unsigned short*>(&h3) << 16);
    ((uint2*)g_xh)[i] = hv;
}
__global__ void cvt_w13_kernel(const float* __restrict__ w) {
    cvt_pair((const float4*)w, (uint2*)g_w13h, (uint2*)g_w13l, NEXP * N1 * HID / 4);
}
__global__ void cvt_w2_kernel(const float* __restrict__ w) {
    cvt_pair((const float4*)w, (uint2*)g_w2h, (uint2*)g_w2l, NEXP * HID * INTER / 4);
}

// ---------------- Router: one warp per token (fp32, exact) ----------------
__global__ __launch_bounds__(256) void router_kernel(const float* __restrict__ x,
                                                     const float* __restrict__ gw) {
    const unsigned FULL = 0xffffffffu;
    int warp = (blockIdx.x * blockDim.x + threadIdx.x) >> 5;
    int lane = threadIdx.x & 31;
    if (warp >= T_TOK) return;
    const int t = warp;
    const float4* x4 = (const float4*)(x + (size_t)t * HID);

    float logit = 0.f;
    for (int e = 0; e < NEXP; e++) {
        const float4* g4 = (const float4*)(gw + (size_t)e * HID);
        float s = 0.f;
        for (int k = lane; k < HID / 4; k += 32) {
            float4 a = x4[k], b = g4[k];
            s += a.x * b.x + a.y * b.y + a.z * b.z + a.w * b.w;
        }
        #pragma unroll
        for (int off = 16; off; off >>= 1) s += __shfl_xor_sync(FULL, s, off);
        if (lane == e) logit = s;
    }
    float m = logit;
    #pragma unroll
    for (int off = 16; off; off >>= 1) m = fmaxf(m, __shfl_xor_sync(FULL, m, off));
    float p = expf(logit - m);
    float sum = p;
    #pragma unroll
    for (int off = 16; off; off >>= 1) sum += __shfl_xor_sync(FULL, sum, off);
    p = p / sum;

    float keep = p, topsum = 0.f;
    int myslot = -1;
    for (int s = 0; s < TOPK; s++) {
        float v = keep; int bl = lane;
        #pragma unroll
        for (int off = 16; off; off >>= 1) {
            float ov = __shfl_down_sync(FULL, v, off);
            int   ol = __shfl_down_sync(FULL, bl, off);
            if (ov > v || (ov == v && ol < bl)) { v = ov; bl = ol; }
        }
        bl = __shfl_sync(FULL, bl, 0);
        v  = __shfl_sync(FULL, v, 0);
        topsum += v;
        if (lane == bl) { myslot = s; keep = -1.f; }
    }
    if (myslot >= 0) {
        int pos = atomicAdd(&g_counts[lane], 1);
        g_list[lane * T_TOK + pos] = t * TOPK + myslot;
        g_pairw[t * TOPK + myslot] = p / topsum;
    }
}

// ================= GEMM1: x(fp16 hi) @ w13(fp16 pair)^T, 2-pass, fused SiLU =================
// CTA 128(M) x 256(N=128 gate + 128 up), K-slab 32, 4-stage, SW64 (64B rows).
// Warp grid 2x4, warp tile 64x64. Stage: Ah[0,8K) Bh[8K,24K) Bl[24K,40K).
__global__ __launch_bounds__(256, 1) void gemm1_mma() {
    const int e  = blockIdx.z;
    const int M  = g_counts[e];
    const int m0 = blockIdx.y * 128;
    if (m0 >= M) return;
    const int t = blockIdx.x;   // 0..3

    extern __shared__ char dsm[];
    int* s_pair = (int*)dsm;
    const uint32_t TILE = smem_u32(dsm) + 1024;
    float* sC = (float*)(dsm + 1024);

    const int tid = threadIdx.x, wid = tid >> 5, lane = tid & 31;
    const int warp_m = wid >> 2, warp_n = wid & 3;

    if (tid < 128) {
        int gr = m0 + tid;
        s_pair[tid] = (gr < M) ? g_list[e * T_TOK + gr] : -1;
    }
    __syncthreads();

    // copy slots: A 512 chunks (2/thread), B 1024 chunks (4/thread); rows are 64B
    uint32_t offA[2], dstA[2]; bool vA[2];
    uint32_t offB[4], dstB[4];
    #pragma unroll
    for (int i = 0; i < 2; i++) {
        int c = tid + i * 256, r = c >> 2, cw = c & 3;
        int p = s_pair[r];
        vA[i] = (p >= 0);
        offA[i] = (uint32_t)(vA[i] ? (p >> 3) : 0) * HID + cw * 8;
        dstA[i] = swz64(r * 64 + cw * 16);
    }
    #pragma unroll
    for (int i = 0; i < 4; i++) {
        int c = tid + i * 256, r = c >> 2, cw = c & 3;
        int brow = (r < 128) ? (t * 128 + r) : (512 + t * 128 + (r - 128));
        offB[i] = ((uint32_t)e * N1 + brow) * HID + cw * 8;
        dstB[i] = swz64(r * 64 + cw * 16);
    }

    auto load_stage = [&](int b, int k0) {
        uint32_t st = TILE + b * ST1;
        #pragma unroll
        for (int i = 0; i < 2; i++)
            cp16(st + dstA[i], g_xh + offA[i] + k0, vA[i]);
        #pragma unroll
        for (int i = 0; i < 4; i++) {
            cp16(st + 8192  + dstB[i], g_w13h + offB[i] + k0, true);
            cp16(st + 24576 + dstB[i], g_w13l + offB[i] + k0, true);
        }
        cp_commit();
    };

    float acc[4][8][4];
    #pragma unroll
    for (int m = 0; m < 4; m++)
        #pragma unroll
        for (int n = 0; n < 8; n++)
            #pragma unroll
            for (int k = 0; k < 4; k++) acc[m][n][k] = 0.f;

    const uint32_t a_row = warp_m * 64 + (lane & 15);
    const uint32_t a_kb  = (lane >> 4) * 16;
    const uint32_t b_row = warp_n * 64 + (lane & 7) + ((lane >> 4) << 3);
    const uint32_t b_kb  = ((lane >> 3) & 1) * 16;

    const int S = HID / KSLAB;  // 48
    load_stage(0, 0);
    load_stage(1, KSLAB);
    load_stage(2, 2 * KSLAB);
    for (int s = 0; s < S; s++) {
        if (s + 2 < S) cp_wait<2>(); else if (s + 1 < S) cp_wait<1>(); else cp_wait<0>();
        __syncthreads();
        if (s + 3 < S) load_stage((s + 3) & 3, (s + 3) * KSLAB);
        const uint32_t st = TILE + (s & 3) * ST1;
        const uint32_t sAh = st, sBh = st + 8192, sBl = st + 24576;
        #pragma unroll
        for (int ks = 0; ks < 2; ks++) {
            uint32_t ah[4][4];
            #pragma unroll
            for (int m = 0; m < 4; m++) {
                uint32_t off = (a_row + m * 16) * 64 + ks * 32 + a_kb;
                ldsm4(ah[m], sAh + swz64(off));
            }
            #pragma unroll
            for (int j = 0; j < 4; j++) {
                uint32_t off = (b_row + j * 16) * 64 + ks * 32 + b_kb;
                uint32_t th[4], tl[4];
                ldsm4(th, sBh + swz64(off));
                ldsm4(tl, sBl + swz64(off));
                #pragma unroll
                for (int m = 0; m < 4; m++) {
                    mma_f16(acc[m][2*j],   ah[m], th);
                    mma_f16(acc[m][2*j],   ah[m], tl);
                    mma_f16(acc[m][2*j+1], ah[m], th + 2);
                    mma_f16(acc[m][2*j+1], ah[m], tl + 2);
                }
            }
        }
    }
    __syncthreads();

    // ---- fused epilogue: gate warps (warp_n<2) stage C via smem; up warps emit fp16 pair h ----
    const int g = lane >> 2, tg = lane & 3;
    if (warp_n < 2) {
        #pragma unroll
        for (int m = 0; m < 4; m++) {
            int row = warp_m * 64 + m * 16 + g;
            #pragma unroll
            for (int n = 0; n < 8; n++) {
                int col = warp_n * 64 + n * 8 + tg * 2;
                sC[row * 132 + col]           = acc[m][n][0];
                sC[row * 132 + col + 1]       = acc[m][n][1];
                sC[(row + 8) * 132 + col]     = acc[m][n][2];
                sC[(row + 8) * 132 + col + 1] = acc[m][n][3];
            }
        }
    }
    __syncthreads();
    if (warp_n >= 2) {
        #pragma unroll
        for (int m = 0; m < 4; m++) {
            int row = warp_m * 64 + m * 16 + g;
            int p0 = s_pair[row], p1 = s_pair[row + 8];
            #pragma unroll
            for (int n = 0; n < 8; n++) {
                int ucol = (warp_n - 2) * 64 + n * 8 + tg * 2;
                if (p0 >= 0) {
                    float g0 = sC[row * 132 + ucol], g1 = sC[row * 132 + ucol + 1];
                    float h0 = g0 / (1.f + expf(-g0)) * acc[m][n][0];
                    float h1 = g1 / (1.f + expf(-g1)) * acc[m][n][1];
                    __half b0 = __float2half_rn(h0), b1 = __float2half_rn(h1);
                    uint32_t o = ((uint32_t)p0 * INTER + t * 128 + ucol) >> 1;
                    ((uint32_t*)g_hh)[o] = (uint32_t)*reinterpret_cast<unsigned short*>(&b0) |
                                           ((uint32_t)*reinterpret_cast<unsigned short*>(&b1) << 16);
                    ((uint32_t*)g_hl)[o] = (uint32_t)hfbits(h0 - __half2float(b0)) |
                                           ((uint32_t)hfbits(h1 - __half2float(b1)) << 16);
                }
                if (p1 >= 0) {
                    float g0 = sC[(row + 8) * 132 + ucol], g1 = sC[(row + 8) * 132 + ucol + 1];
                    float h0 = g0 / (1.f + expf(-g0)) * acc[m][n][2];
                    float h1 = g1 / (1.f + expf(-g1)) * acc[m][n][3];
                    __half b0 = __float2half_rn(h0), b1 = __float2half_rn(h1);
                    uint32_t o = ((uint32_t)p1 * INTER + t * 128 + ucol) >> 1;
                    ((uint32_t*)g_hh)[o] = (uint32_t)*reinterpret_cast<unsigned short*>(&b0) |
                                           ((uint32_t)*reinterpret_cast<unsigned short*>(&b1) << 16);
                    ((uint32_t*)g_hl)[o] = (uint32_t)hfbits(h0 - __half2float(b0)) |
                                           ((uint32_t)hfbits(h1 - __half2float(b1)) << 16);
                }
            }
        }
    }
}

// ================= GEMM2: h(fp16 pair) @ w2(fp16 pair)^T, 3-pass, scaled =================
// CTA 128 x 256, K-slab 32, 4-stage. Stage: Ah[0,8K) Al[8K,16K) Bh[16K,32K) Bl[32K,48K).
__global__ __launch_bounds__(256, 1) void gemm2_mma() {
    const int e  = blockIdx.z;
    const int M  = g_counts[e];
    const int m0 = blockIdx.y * 128;
    if (m0 >= M) return;
    const int n0 = blockIdx.x * 256;

    extern __shared__ char dsm[];
    int* s_pair = (int*)dsm;
    const uint32_t TILE = smem_u32(dsm) + 1024;

    const int tid = threadIdx.x, wid = tid >> 5, lane = tid & 31;
    const int warp_m = wid >> 2, warp_n = wid & 3;

    if (tid < 128) {
        int gr = m0 + tid;
        s_pair[tid] = (gr < M) ? g_list[e * T_TOK + gr] : -1;
    }
    __syncthreads();

    uint32_t offA[2], dstA[2]; bool vA[2];
    uint32_t offB[4], dstB[4];
    #pragma unroll
    for (int i = 0; i < 2; i++) {
        int c = tid + i * 256, r = c >> 2, cw = c & 3;
        int p = s_pair[r];
        vA[i] = (p >= 0);
        offA[i] = (uint32_t)(vA[i] ? p : 0) * INTER + cw * 8;
        dstA[i] = swz64(r * 64 + cw * 16);
    }
    #pragma unroll
    for (int i = 0; i < 4; i++) {
        int c = tid + i * 256, r = c >> 2, cw = c & 3;
        offB[i] = ((uint32_t)e * HID + n0 + r) * INTER + cw * 8;
        dstB[i] = swz64(r * 64 + cw * 16);
    }

    auto load_stage = [&](int b, int k0) {
        uint32_t st = TILE + b * ST2;
        #pragma unroll
        for (int i = 0; i < 2; i++) {
            cp16(st + dstA[i],        g_hh + offA[i] + k0, vA[i]);
            cp16(st + 8192 + dstA[i], g_hl + offA[i] + k0, vA[i]);
        }
        #pragma unroll
        for (int i = 0; i < 4; i++) {
            cp16(st + 16384 + dstB[i], g_w2h + offB[i] + k0, true);
            cp16(st + 32768 + dstB[i], g_w2l + offB[i] + k0, true);
        }
        cp_commit();
    };

    float acc[4][8][4];
    #pragma unroll
    for (int m = 0; m < 4; m++)
        #pragma unroll
        for (int n = 0; n < 8; n++)
            #pragma unroll
            for (int k = 0; k < 4; k++) acc[m][n][k] = 0.f;

    const uint32_t a_row = warp_m * 64 + (lane & 15);
    const uint32_t a_kb  = (lane >> 4) * 16;
    const uint32_t b_row = warp_n * 64 + (lane & 7) + ((lane >> 4) << 3);
    const uint32_t b_kb  = ((lane >> 3) & 1) * 16;

    const int S = INTER / KSLAB;  // 16
    load_stage(0, 0);
    load_stage(1, KSLAB);
    load_stage(2, 2 * KSLAB);
    for (int s = 0; s < S; s++) {
        if (s + 2 < S) cp_wait<2>(); else if (s + 1 < S) cp_wait<1>(); else cp_wait<0>();
        __syncthreads();
        if (s + 3 < S) load_stage((s + 3) & 3, (s + 3) * KSLAB);
        const uint32_t st = TILE + (s & 3) * ST2;
        const uint32_t sAh = st, sAl = st + 8192, sBh = st + 16384, sBl = st + 32768;
        #pragma unroll
        for (int ks = 0; ks < 2; ks++) {
            uint32_t ah[4][4], al[4][4];
            #pragma unroll
            for (int m = 0; m < 4; m++) {
                uint32_t off = (a_row + m * 16) * 64 + ks * 32 + a_kb;
                ldsm4(ah[m], sAh + swz64(off));
                ldsm4(al[m], sAl + swz64(off));
            }
            #pragma unroll
            for (int j = 0; j < 4; j++) {
                uint32_t off = (b_row + j * 16) * 64 + ks * 32 + b_kb;
                uint32_t th[4], tl[4];
                ldsm4(th, sBh + swz64(off));
                ldsm4(tl, sBl + swz64(off));
                #pragma unroll
                for (int m = 0; m < 4; m++) {
                    mma_f16(acc[m][2*j],   ah[m], th);
                    mma_f16(acc[m][2*j],   ah[m], tl);
                    mma_f16(acc[m][2*j],   al[m], th);
                    mma_f16(acc[m][2*j+1], ah[m], th + 2);
                    mma_f16(acc[m][2*j+1], ah[m], tl + 2);
                    mma_f16(acc[m][2*j+1], al[m], th + 2);
                }
            }
        }
    }

    const int g = lane >> 2, tg = lane & 3;
    #pragma unroll
    for (int m = 0; m < 4; m++) {
        int lr = warp_m * 64 + m * 16 + g;
        int p0 = s_pair[lr], p1 = s_pair[lr + 8];
        float w0 = (p0 >= 0) ? g_pairw[p0] : 0.f;
        float w1 = (p1 >= 0) ? g_pairw[p1] : 0.f;
        #pragma unroll
        for (int n = 0; n < 8; n++) {
            int col = n0 + warp_n * 64 + n * 8 + tg * 2;
            if (p0 >= 0) *(float2*)(g_y + (size_t)p0 * HID + col) = make_float2(w0 * acc[m][n][0], w0 * acc[m][n][1]);
            if (p1 >= 0) *(float2*)(g_y + (size_t)p1 * HID + col) = make_float2(w1 * acc[m][n][2], w1 * acc[m][n][3]);
        }
    }
}

// ---------------- deterministic 8-slot reduction ----------------
__global__ void reduce_kernel(float* __restrict__ out) {
    size_t idx = (size_t)blockIdx.x * blockDim.x + threadIdx.x;
    const size_t total = (size_t)T_TOK * (HID / 4);
    if (idx >= total) return;
    size_t t = idx / (HID / 4);
    int    c = (int)(idx % (HID / 4));
    const float4* base = (const float4*)(g_y + t * (size_t)TOPK * HID) + c;
    float4 s = make_float4(0.f, 0.f, 0.f, 0.f);
    #pragma unroll
    for (int sl = 0; sl < TOPK; sl++) {
        float4 v = base[(size_t)sl * (HID / 4)];
        s.x += v.x; s.y += v.y; s.z += v.z; s.w += v.w;
    }
    ((float4*)out)[idx] = s;
}

extern "C" void kernel_launch(void* const* d_in, const int* in_sizes, int n_in,
                              void* d_out, int out_size) {
    (void)in_sizes; (void)n_in; (void)out_size;
    const float* x   = (const float*)d_in[0];
    const float* gw  = (const float*)d_in[1];
    const float* w13 = (const float*)d_in[2];
    const float* w2  = (const float*)d_in[3];
    float* out = (float*)d_out;

    cudaFuncSetAttribute(gemm1_mma, cudaFuncAttributeMaxDynamicSharedMemorySize, SMEM1);
    cudaFuncSetAttribute(gemm2_mma, cudaFuncAttributeMaxDynamicSharedMemorySize, SMEM2);

    reset_kernel<<<1, 32>>>();
    cvt_x_kernel<<<(T_TOK * HID / 4 + 255) / 256, 256>>>(x);
    cvt_w13_kernel<<<(NEXP * N1 * HID / 4 + 255) / 256, 256>>>(w13);
    cvt_w2_kernel<<<(NEXP * HID * INTER / 4 + 255) / 256, 256>>>(w2);
    router_kernel<<<T_TOK / 8, 256>>>(x, gw);
    gemm1_mma<<<dim3(INTER / 128, 64, NEXP), 256, SMEM1>>>();
    gemm2_mma<<<dim3(HID / 256, 64, NEXP), 256, SMEM2>>>();
    reduce_kernel<<<(int)(((size_t)T_TOK * (HID / 4)) / 256), 256>>>(out);
}

// round 8
// speedup vs baseline: 2.3784x; 1.8352x over previous
#include <cuda_runtime.h>
#include <cuda_fp16.h>
#include <cstdint>

#define T_TOK 8192
#define HID   1536
#define NEXP  32
#define TOPK  8
#define INTER 512
#define N1    (2*INTER)       // 1024
#define MAXP  (T_TOK*TOPK)    // 65536

#define KSLAB 64
#define STG   49152           // Ah16K + Bh32K
#define SMEMG (1024 + 4*STG)  // 197632

// ---------------- device scratch ----------------
__device__ int   g_counts[NEXP];
__device__ int   g_list[NEXP * T_TOK];
__device__ float g_pairw[MAXP];
__device__ __half g_xh[(size_t)T_TOK * HID];
__device__ __half g_w13h[(size_t)NEXP * N1 * HID];
__device__ __half g_w2h[(size_t)NEXP * HID * INTER];
__device__ __half g_hh[(size_t)MAXP * INTER];
__device__ float g_y[(size_t)MAXP * HID];

// ---------------- PTX helpers (sm_103-baseline safe) ----------------
__device__ __forceinline__ uint32_t smem_u32(const void* p) {
    uint32_t a;
    asm("{ .reg .u64 t; cvta.to.shared.u64 t, %1; cvt.u32.u64 %0, t; }" : "=r"(a) : "l"(p));
    return a;
}
__device__ __forceinline__ uint32_t swz(uint32_t b) { return b ^ ((b >> 3) & 0x70); }

__device__ __forceinline__ void cp16(uint32_t dst, const void* src, bool valid) {
    int sz = valid ? 16 : 0;
    asm volatile("cp.async.cg.shared.global [%0], [%1], 16, %2;\n" :: "r"(dst), "l"(src), "r"(sz));
}
__device__ __forceinline__ void cp_commit() { asm volatile("cp.async.commit_group;" ::: "memory"); }
template <int N> __device__ __forceinline__ void cp_wait() {
    asm volatile("cp.async.wait_group %0;" :: "n"(N) : "memory");
}
__device__ __forceinline__ void ldsm4(uint32_t* r, uint32_t addr) {
    asm volatile("ldmatrix.sync.aligned.m8n8.x4.shared.b16 {%0,%1,%2,%3}, [%4];"
                 : "=r"(r[0]), "=r"(r[1]), "=r"(r[2]), "=r"(r[3]) : "r"(addr));
}
__device__ __forceinline__ void mma_f16(float* c, const uint32_t* a, const uint32_t* b) {
    asm volatile("mma.sync.aligned.m16n8k16.row.col.f32.f16.f16.f32 "
                 "{%0,%1,%2,%3}, {%4,%5,%6,%7}, {%8,%9}, {%0,%1,%2,%3};"
                 : "+f"(c[0]), "+f"(c[1]), "+f"(c[2]), "+f"(c[3])
                 : "r"(a[0]), "r"(a[1]), "r"(a[2]), "r"(a[3]), "r"(b[0]), "r"(b[1]));
}

// ---------------- reset ----------------
__global__ void reset_kernel() {
    if (threadIdx.x < NEXP) g_counts[threadIdx.x] = 0;
}

// ---------------- fp32 -> fp16 (hi only) ----------------
__device__ __forceinline__ void cvt_hi(const float4* __restrict__ src, uint2* __restrict__ hi, int n4) {
    int i = blockIdx.x * blockDim.x + threadIdx.x;
    if (i >= n4) return;
    float4 v = src[i];
    __half h0 = __float2half_rn(v.x), h1 = __float2half_rn(v.y);
    __half h2 = __float2half_rn(v.z), h3 = __float2half_rn(v.w);
    uint2 hv;
    hv.x = (uint32_t)*reinterpret_cast<unsigned short*>(&h0) | ((uint32_t)*reinterpret_cast<unsigned short*>(&h1) << 16);
    hv.y = (uint32_t)*reinterpret_cast<unsigned short*>(&h2) | ((uint32_t)*reinterpret_cast<unsigned short*>(&h3) << 16);
    hi[i] = hv;
}
__global__ void cvt_x_kernel(const float* __restrict__ x) {
    cvt_hi((const float4*)x, (uint2*)g_xh, T_TOK * HID / 4);
}
__global__ void cvt_w13_kernel(const float* __restrict__ w) {
    cvt_hi((const float4*)w, (uint2*)g_w13h, NEXP * N1 * HID / 4);
}
__global__ void cvt_w2_kernel(const float* __restrict__ w) {
    cvt_hi((const float4*)w, (uint2*)g_w2h, NEXP * HID * INTER / 4);
}

// ---------------- Router: one warp per token (fp32, exact) ----------------
__global__ __launch_bounds__(256) void router_kernel(const float* __restrict__ x,
                                                     const float* __restrict__ gw) {
    const unsigned FULL = 0xffffffffu;
    int warp = (blockIdx.x * blockDim.x + threadIdx.x) >> 5;
    int lane = threadIdx.x & 31;
    if (warp >= T_TOK) return;
    const int t = warp;
    const float4* x4 = (const float4*)(x + (size_t)t * HID);

    float logit = 0.f;
    for (int e = 0; e < NEXP; e++) {
        const float4* g4 = (const float4*)(gw + (size_t)e * HID);
        float s = 0.f;
        for (int k = lane; k < HID / 4; k += 32) {
            float4 a = x4[k], b = g4[k];
            s += a.x * b.x + a.y * b.y + a.z * b.z + a.w * b.w;
        }
        #pragma unroll
        for (int off = 16; off; off >>= 1) s += __shfl_xor_sync(FULL, s, off);
        if (lane == e) logit = s;
    }
    float m = logit;
    #pragma unroll
    for (int off = 16; off; off >>= 1) m = fmaxf(m, __shfl_xor_sync(FULL, m, off));
    float p = expf(logit - m);
    float sum = p;
    #pragma unroll
    for (int off = 16; off; off >>= 1) sum += __shfl_xor_sync(FULL, sum, off);
    p = p / sum;

    float keep = p, topsum = 0.f;
    int myslot = -1;
    for (int s = 0; s < TOPK; s++) {
        float v = keep; int bl = lane;
        #pragma unroll
        for (int off = 16; off; off >>= 1) {
            float ov = __shfl_down_sync(FULL, v, off);
            int   ol = __shfl_down_sync(FULL, bl, off);
            if (ov > v || (ov == v && ol < bl)) { v = ov; bl = ol; }
        }
        bl = __shfl_sync(FULL, bl, 0);
        v  = __shfl_sync(FULL, v, 0);
        topsum += v;
        if (lane == bl) { myslot = s; keep = -1.f; }
    }
    if (myslot >= 0) {
        int pos = atomicAdd(&g_counts[lane], 1);
        g_list[lane * T_TOK + pos] = t * TOPK + myslot;
        g_pairw[t * TOPK + myslot] = p / topsum;
    }
}

// ================= GEMM1: x(fp16) @ w13(fp16)^T, single-pass, fused SiLU =================
// CTA 128(M) x 256(N=128 gate + 128 up), K-slab 64, 4-stage, SW128 (128B rows).
// Warp grid 2x4, warp tile 64x64. Stage: Ah[0,16K) Bh[16K,48K).
__global__ __launch_bounds__(256, 1) void gemm1_mma() {
    const int e  = blockIdx.z;
    const int M  = g_counts[e];
    const int m0 = blockIdx.y * 128;
    if (m0 >= M) return;
    const int t = blockIdx.x;   // 0..3

    extern __shared__ char dsm[];
    int* s_pair = (int*)dsm;
    const uint32_t TILE = smem_u32(dsm) + 1024;
    float* sC = (float*)(dsm + 1024);

    const int tid = threadIdx.x, wid = tid >> 5, lane = tid & 31;
    const int warp_m = wid >> 2, warp_n = wid & 3;

    if (tid < 128) {
        int gr = m0 + tid;
        s_pair[tid] = (gr < M) ? g_list[e * T_TOK + gr] : -1;
    }
    __syncthreads();

    // copy slots: A 1024 chunks (4/thread), B 2048 chunks (8/thread); 128B rows
    uint32_t offA[4], dstA[4]; bool vA[4];
    uint32_t offB[8], dstB[8];
    #pragma unroll
    for (int i = 0; i < 4; i++) {
        int c = tid + i * 256, r = c >> 3, cw = c & 7;
        int p = s_pair[r];
        vA[i] = (p >= 0);
        offA[i] = (uint32_t)(vA[i] ? (p >> 3) : 0) * HID + cw * 8;
        dstA[i] = swz(r * 128 + cw * 16);
    }
    #pragma unroll
    for (int i = 0; i < 8; i++) {
        int c = tid + i * 256, r = c >> 3, cw = c & 7;
        int brow = (r < 128) ? (t * 128 + r) : (512 + t * 128 + (r - 128));
        offB[i] = ((uint32_t)e * N1 + brow) * HID + cw * 8;
        dstB[i] = swz(r * 128 + cw * 16);
    }

    auto load_stage = [&](int b, int k0) {
        uint32_t st = TILE + b * STG;
        #pragma unroll
        for (int i = 0; i < 4; i++)
            cp16(st + dstA[i], g_xh + offA[i] + k0, vA[i]);
        #pragma unroll
        for (int i = 0; i < 8; i++)
            cp16(st + 16384 + dstB[i], g_w13h + offB[i] + k0, true);
        cp_commit();
    };

    float acc[4][8][4];
    #pragma unroll
    for (int m = 0; m < 4; m++)
        #pragma unroll
        for (int n = 0; n < 8; n++)
            #pragma unroll
            for (int k = 0; k < 4; k++) acc[m][n][k] = 0.f;

    const uint32_t a_row = warp_m * 64 + (lane & 15);
    const uint32_t a_kb  = (lane >> 4) * 16;
    const uint32_t b_row = warp_n * 64 + (lane & 7) + ((lane >> 4) << 3);
    const uint32_t b_kb  = ((lane >> 3) & 1) * 16;

    const int S = HID / KSLAB;  // 24
    load_stage(0, 0);
    load_stage(1, KSLAB);
    load_stage(2, 2 * KSLAB);
    for (int s = 0; s < S; s++) {
        if (s + 2 < S) cp_wait<2>(); else if (s + 1 < S) cp_wait<1>(); else cp_wait<0>();
        __syncthreads();
        if (s + 3 < S) load_stage((s + 3) & 3, (s + 3) * KSLAB);
        const uint32_t st = TILE + (s & 3) * STG;
        const uint32_t sAh = st, sBh = st + 16384;
        #pragma unroll
        for (int ks = 0; ks < 4; ks++) {
            uint32_t ah[4][4];
            #pragma unroll
            for (int m = 0; m < 4; m++) {
                uint32_t off = (a_row + m * 16) * 128 + ks * 32 + a_kb;
                ldsm4(ah[m], sAh + swz(off));
            }
            #pragma unroll
            for (int j = 0; j < 4; j++) {
                uint32_t off = (b_row + j * 16) * 128 + ks * 32 + b_kb;
                uint32_t th[4];
                ldsm4(th, sBh + swz(off));
                #pragma unroll
                for (int m = 0; m < 4; m++) {
                    mma_f16(acc[m][2*j],   ah[m], th);
                    mma_f16(acc[m][2*j+1], ah[m], th + 2);
                }
            }
        }
    }
    __syncthreads();

    // ---- fused epilogue: gate warps (warp_n<2) stage C via smem; up warps emit fp16 h ----
    const int g = lane >> 2, tg = lane & 3;
    if (warp_n < 2) {
        #pragma unroll
        for (int m = 0; m < 4; m++) {
            int row = warp_m * 64 + m * 16 + g;
            #pragma unroll
            for (int n = 0; n < 8; n++) {
                int col = warp_n * 64 + n * 8 + tg * 2;
                sC[row * 132 + col]           = acc[m][n][0];
                sC[row * 132 + col + 1]       = acc[m][n][1];
                sC[(row + 8) * 132 + col]     = acc[m][n][2];
                sC[(row + 8) * 132 + col + 1] = acc[m][n][3];
            }
        }
    }
    __syncthreads();
    if (warp_n >= 2) {
        #pragma unroll
        for (int m = 0; m < 4; m++) {
            int row = warp_m * 64 + m * 16 + g;
            int p0 = s_pair[row], p1 = s_pair[row + 8];
            #pragma unroll
            for (int n = 0; n < 8; n++) {
                int ucol = (warp_n - 2) * 64 + n * 8 + tg * 2;
                if (p0 >= 0) {
                    float g0 = sC[row * 132 + ucol], g1 = sC[row * 132 + ucol + 1];
                    float h0 = g0 / (1.f + expf(-g0)) * acc[m][n][0];
                    float h1 = g1 / (1.f + expf(-g1)) * acc[m][n][1];
                    __half b0 = __float2half_rn(h0), b1 = __float2half_rn(h1);
                    uint32_t o = ((uint32_t)p0 * INTER + t * 128 + ucol) >> 1;
                    ((uint32_t*)g_hh)[o] = (uint32_t)*reinterpret_cast<unsigned short*>(&b0) |
                                           ((uint32_t)*reinterpret_cast<unsigned short*>(&b1) << 16);
                }
                if (p1 >= 0) {
                    float g0 = sC[(row + 8) * 132 + ucol], g1 = sC[(row + 8) * 132 + ucol + 1];
                    float h0 = g0 / (1.f + expf(-g0)) * acc[m][n][2];
                    float h1 = g1 / (1.f + expf(-g1)) * acc[m][n][3];
                    __half b0 = __float2half_rn(h0), b1 = __float2half_rn(h1);
                    uint32_t o = ((uint32_t)p1 * INTER + t * 128 + ucol) >> 1;
                    ((uint32_t*)g_hh)[o] = (uint32_t)*reinterpret_cast<unsigned short*>(&b0) |
                                           ((uint32_t)*reinterpret_cast<unsigned short*>(&b1) << 16);
                }
            }
        }
    }
}

// ================= GEMM2: h(fp16) @ w2(fp16)^T, single-pass, scaled =================
// CTA 128 x 256, K-slab 64, 4-stage, SW128. Stage: Ah[0,16K) Bh[16K,48K).
__global__ __launch_bounds__(256, 1) void gemm2_mma() {
    const int e  = blockIdx.z;
    const int M  = g_counts[e];
    const int m0 = blockIdx.y * 128;
    if (m0 >= M) return;
    const int n0 = blockIdx.x * 256;

    extern __shared__ char dsm[];
    int* s_pair = (int*)dsm;
    const uint32_t TILE = smem_u32(dsm) + 1024;

    const int tid = threadIdx.x, wid = tid >> 5, lane = tid & 31;
    const int warp_m = wid >> 2, warp_n = wid & 3;

    if (tid < 128) {
        int gr = m0 + tid;
        s_pair[tid] = (gr < M) ? g_list[e * T_TOK + gr] : -1;
    }
    __syncthreads();

    uint32_t offA[4], dstA[4]; bool vA[4];
    uint32_t offB[8], dstB[8];
    #pragma unroll
    for (int i = 0; i < 4; i++) {
        int c = tid + i * 256, r = c >> 3, cw = c & 7;
        int p = s_pair[r];
        vA[i] = (p >= 0);
        offA[i] = (uint32_t)(vA[i] ? p : 0) * INTER + cw * 8;
        dstA[i] = swz(r * 128 + cw * 16);
    }
    #pragma unroll
    for (int i = 0; i < 8; i++) {
        int c = tid + i * 256, r = c >> 3, cw = c & 7;
        offB[i] = ((uint32_t)e * HID + n0 + r) * INTER + cw * 8;
        dstB[i] = swz(r * 128 + cw * 16);
    }

    auto load_stage = [&](int b, int k0) {
        uint32_t st = TILE + b * STG;
        #pragma unroll
        for (int i = 0; i < 4; i++)
            cp16(st + dstA[i], g_hh + offA[i] + k0, vA[i]);
        #pragma unroll
        for (int i = 0; i < 8; i++)
            cp16(st + 16384 + dstB[i], g_w2h + offB[i] + k0, true);
        cp_commit();
    };

    float acc[4][8][4];
    #pragma unroll
    for (int m = 0; m < 4; m++)
        #pragma unroll
        for (int n = 0; n < 8; n++)
            #pragma unroll
            for (int k = 0; k < 4; k++) acc[m][n][k] = 0.f;

    const uint32_t a_row = warp_m * 64 + (lane & 15);
    const uint32_t a_kb  = (lane >> 4) * 16;
    const uint32_t b_row = warp_n * 64 + (lane & 7) + ((lane >> 4) << 3);
    const uint32_t b_kb  = ((lane >> 3) & 1) * 16;

    const int S = INTER / KSLAB;  // 8
    load_stage(0, 0);
    load_stage(1, KSLAB);
    load_stage(2, 2 * KSLAB);
    for (int s = 0; s < S; s++) {
        if (s + 2 < S) cp_wait<2>(); else if (s + 1 < S) cp_wait<1>(); else cp_wait<0>();
        __syncthreads();
        if (s + 3 < S) load_stage((s + 3) & 3, (s + 3) * KSLAB);
        const uint32_t st = TILE + (s & 3) * STG;
        const uint32_t sAh = st, sBh = st + 16384;
        #pragma unroll
        for (int ks = 0; ks < 4; ks++) {
            uint32_t ah[4][4];
            #pragma unroll
            for (int m = 0; m < 4; m++) {
                uint32_t off = (a_row + m * 16) * 128 + ks * 32 + a_kb;
                ldsm4(ah[m], sAh + swz(off));
            }
            #pragma unroll
            for (int j = 0; j < 4; j++) {
                uint32_t off = (b_row + j * 16) * 128 + ks * 32 + b_kb;
                uint32_t th[4];
                ldsm4(th, sBh + swz(off));
                #pragma unroll
                for (int m = 0; m < 4; m++) {
                    mma_f16(acc[m][2*j],   ah[m], th);
                    mma_f16(acc[m][2*j+1], ah[m], th + 2);
                }
            }
        }
    }

    const int g = lane >> 2, tg = lane & 3;
    #pragma unroll
    for (int m = 0; m < 4; m++) {
        int lr = warp_m * 64 + m * 16 + g;
        int p0 = s_pair[lr], p1 = s_pair[lr + 8];
        float w0 = (p0 >= 0) ? g_pairw[p0] : 0.f;
        float w1 = (p1 >= 0) ? g_pairw[p1] : 0.f;
        #pragma unroll
        for (int n = 0; n < 8; n++) {
            int col = n0 + warp_n * 64 + n * 8 + tg * 2;
            if (p0 >= 0) *(float2*)(g_y + (size_t)p0 * HID + col) = make_float2(w0 * acc[m][n][0], w0 * acc[m][n][1]);
            if (p1 >= 0) *(float2*)(g_y + (size_t)p1 * HID + col) = make_float2(w1 * acc[m][n][2], w1 * acc[m][n][3]);
        }
    }
}

// ---------------- deterministic 8-slot reduction ----------------
__global__ void reduce_kernel(float* __restrict__ out) {
    size_t idx = (size_t)blockIdx.x * blockDim.x + threadIdx.x;
    const size_t total = (size_t)T_TOK * (HID / 4);
    if (idx >= total) return;
    size_t t = idx / (HID / 4);
    int    c = (int)(idx % (HID / 4));
    const float4* base = (const float4*)(g_y + t * (size_t)TOPK * HID) + c;
    float4 s = make_float4(0.f, 0.f, 0.f, 0.f);
    #pragma unroll
    for (int sl = 0; sl < TOPK; sl++) {
        float4 v = base[(size_t)sl * (HID / 4)];
        s.x += v.x; s.y += v.y; s.z += v.z; s.w += v.w;
    }
    ((float4*)out)[idx] = s;
}

extern "C" void kernel_launch(void* const* d_in, const int* in_sizes, int n_in,
                              void* d_out, int out_size) {
    (void)in_sizes; (void)n_in; (void)out_size;
    const float* x   = (const float*)d_in[0];
    const float* gw  = (const float*)d_in[1];
    const float* w13 = (const float*)d_in[2];
    const float* w2  = (const float*)d_in[3];
    float* out = (float*)d_out;

    cudaFuncSetAttribute(gemm1_mma, cudaFuncAttributeMaxDynamicSharedMemorySize, SMEMG);
    cudaFuncSetAttribute(gemm2_mma, cudaFuncAttributeMaxDynamicSharedMemorySize, SMEMG);

    reset_kernel<<<1, 32>>>();
    cvt_x_kernel<<<(T_TOK * HID / 4 + 255) / 256, 256>>>(x);
    cvt_w13_kernel<<<(NEXP * N1 * HID / 4 + 255) / 256, 256>>>(w13);
    cvt_w2_kernel<<<(NEXP * HID * INTER / 4 + 255) / 256, 256>>>(w2);
    router_kernel<<<T_TOK / 8, 256>>>(x, gw);
    gemm1_mma<<<dim3(INTER / 128, 64, NEXP), 256, SMEMG>>>();
    gemm2_mma<<<dim3(HID / 256, 64, NEXP), 256, SMEMG>>>();
    reduce_kernel<<<(int)(((size_t)T_TOK * (HID / 4)) / 256), 256>>>(out);
}